// round 2
// baseline (speedup 1.0000x reference)
#include <cuda_runtime.h>
#include <math.h>

// Problem constants
#define Bb   16
#define Tt   16
#define Ll   512
#define Hdim 768

// SELU constants (jax.nn.selu)
#define SELU_SCALE 1.0507009873554805f
#define SELU_SA    1.7580993408473766f   // scale * alpha

// Scratch (module-static device globals; no allocation at runtime)
__device__ float g_WE[(size_t)Bb * Ll * Hdim];   // [B*L, H] = hn @ W1^T
__device__ float g_WD[(size_t)Bb * Tt * Hdim];   // [B*T, H] = dj @ W2^T

// Detect index dtype: int32 -> word[1] = Xindex[0,1] = 32 (nonzero);
// int64 little-endian -> word[1] is the high word of Xindex[0,0] = 0.
__device__ __forceinline__ int idx_stride(const int* __restrict__ xp) {
    return (xp[1] == 0) ? 2 : 1;
}

// ---------------------------------------------------------------------------
// Kernel A: WE = hn @ W1^T   (M=8192, N=768, K=768)
// 128x128 tile, BK=16, 256 threads, 8x8 microtile.
// ---------------------------------------------------------------------------
__global__ __launch_bounds__(256) void we_gemm_kernel(
    const float* __restrict__ A,   // hn [8192, 768]
    const float* __restrict__ W)   // W1 [768, 768]
{
    __shared__ float As[16][132];
    __shared__ float Bs[16][132];

    const int tid = threadIdx.x;
    const int m0 = blockIdx.y * 128;
    const int n0 = blockIdx.x * 128;
    const int tm = (tid >> 4) * 8;
    const int tn = (tid & 15) * 8;

    float acc[8][8];
#pragma unroll
    for (int i = 0; i < 8; i++)
#pragma unroll
        for (int j = 0; j < 8; j++) acc[i][j] = 0.f;

    for (int k0 = 0; k0 < Hdim; k0 += 16) {
#pragma unroll
        for (int i = 0; i < 2; i++) {
            int id  = tid + i * 256;
            int row = id >> 2;
            int kg  = (id & 3) * 4;
            float4 va = *(const float4*)(A + (size_t)(m0 + row) * Hdim + k0 + kg);
            As[kg + 0][row] = va.x; As[kg + 1][row] = va.y;
            As[kg + 2][row] = va.z; As[kg + 3][row] = va.w;
            float4 vb = *(const float4*)(W + (size_t)(n0 + row) * Hdim + k0 + kg);
            Bs[kg + 0][row] = vb.x; Bs[kg + 1][row] = vb.y;
            Bs[kg + 2][row] = vb.z; Bs[kg + 3][row] = vb.w;
        }
        __syncthreads();

#pragma unroll
        for (int kk = 0; kk < 16; kk++) {
            float a[8], b[8];
            *(float4*)&a[0] = *(const float4*)&As[kk][tm];
            *(float4*)&a[4] = *(const float4*)&As[kk][tm + 4];
            *(float4*)&b[0] = *(const float4*)&Bs[kk][tn];
            *(float4*)&b[4] = *(const float4*)&Bs[kk][tn + 4];
#pragma unroll
            for (int i = 0; i < 8; i++)
#pragma unroll
                for (int j = 0; j < 8; j++)
                    acc[i][j] = fmaf(a[i], b[j], acc[i][j]);
        }
        __syncthreads();
    }

#pragma unroll
    for (int i = 0; i < 8; i++) {
        float4 o0, o1;
        o0.x = acc[i][0]; o0.y = acc[i][1]; o0.z = acc[i][2]; o0.w = acc[i][3];
        o1.x = acc[i][4]; o1.y = acc[i][5]; o1.z = acc[i][6]; o1.w = acc[i][7];
        float* cp = g_WE + (size_t)(m0 + tm + i) * Hdim + n0 + tn;
        *(float4*)(cp)     = o0;
        *(float4*)(cp + 4) = o1;
    }
}

// ---------------------------------------------------------------------------
// Kernel B: WD[r,:] = decoder_out[b, Yindex[b,t], :] @ W2^T
// M=256 (gathered rows), N=768, K=768. 64x64 tile, BK=16, 4x4 microtile.
// ---------------------------------------------------------------------------
__global__ __launch_bounds__(256) void wd_gemm_kernel(
    const float* __restrict__ D,    // decoder_out [16, 512, 768]
    const float* __restrict__ W2,   // [768, 768]
    const int*   __restrict__ xp,   // Xindex (for dtype detection)
    const int*   __restrict__ yp)   // Yindex
{
    __shared__ float As[16][68];
    __shared__ float Bs[16][68];

    const int st  = idx_stride(xp);
    const int tid = threadIdx.x;
    const int m0  = blockIdx.y * 64;
    const int n0  = blockIdx.x * 64;
    const int tm  = (tid >> 4) * 4;
    const int tn  = (tid & 15) * 4;

    // One float4 per thread per tile-load; row is fixed across k-iterations.
    const int row = tid >> 2;
    const int kg  = (tid & 3) * 4;
    const int r   = m0 + row;                 // global (b*T+t) row 0..255
    const int bi  = r >> 4;                   // r / T
    const int Yv  = yp[r * st];               // gather index (< 512)
    const float* arow = D + ((size_t)bi * Ll + (size_t)Yv) * Hdim;
    const float* brow = W2 + (size_t)(n0 + row) * Hdim;

    float acc[4][4];
#pragma unroll
    for (int i = 0; i < 4; i++)
#pragma unroll
        for (int j = 0; j < 4; j++) acc[i][j] = 0.f;

    for (int k0 = 0; k0 < Hdim; k0 += 16) {
        float4 va = *(const float4*)(arow + k0 + kg);
        As[kg + 0][row] = va.x; As[kg + 1][row] = va.y;
        As[kg + 2][row] = va.z; As[kg + 3][row] = va.w;
        float4 vb = *(const float4*)(brow + k0 + kg);
        Bs[kg + 0][row] = vb.x; Bs[kg + 1][row] = vb.y;
        Bs[kg + 2][row] = vb.z; Bs[kg + 3][row] = vb.w;
        __syncthreads();

#pragma unroll
        for (int kk = 0; kk < 16; kk++) {
            float a[4], b[4];
            *(float4*)&a[0] = *(const float4*)&As[kk][tm];
            *(float4*)&b[0] = *(const float4*)&Bs[kk][tn];
#pragma unroll
            for (int i = 0; i < 4; i++)
#pragma unroll
                for (int j = 0; j < 4; j++)
                    acc[i][j] = fmaf(a[i], b[j], acc[i][j]);
        }
        __syncthreads();
    }

#pragma unroll
    for (int i = 0; i < 4; i++) {
        float4 o;
        o.x = acc[i][0]; o.y = acc[i][1]; o.z = acc[i][2]; o.w = acc[i][3];
        *(float4*)(g_WD + (size_t)(m0 + tm + i) * Hdim + n0 + tn) = o;
    }
}

// ---------------------------------------------------------------------------
// Kernel C: per-(b,t) pointer scores + masked log-softmax + NLL accumulation.
// One block per (b,t). Warp-per-l over the valid region [X, 512).
// ---------------------------------------------------------------------------
__device__ __forceinline__ float selu1(float x) {
    float e = __expf(x);
    return (x > 0.f) ? SELU_SCALE * x : fmaf(SELU_SA, e, -SELU_SA);
}

__global__ __launch_bounds__(256) void pointer_kernel(
    const float* __restrict__ V,
    const int*   __restrict__ xp,
    const int*   __restrict__ yp,
    float*       __restrict__ out)
{
    __shared__ float scores[Ll];
    __shared__ float redm[8];
    __shared__ float reds[8];

    const int bt   = blockIdx.x;          // b*T + t
    const int b    = bt >> 4;
    const int tid  = threadIdx.x;
    const int lane = tid & 31;
    const int warp = tid >> 5;

    const int st = idx_stride(xp);
    const int X  = xp[bt * st];
    const int Y  = yp[bt * st];

    // Per-lane register fragments of WD[bt,:] and V: h = 4*(lane + 32*k)
    float4 wdf[6], vf[6];
    const float4* wdp = (const float4*)(g_WD + (size_t)bt * Hdim);
    const float4* vp  = (const float4*)V;
#pragma unroll
    for (int k = 0; k < 6; k++) {
        wdf[k] = wdp[lane + 32 * k];
        vf[k]  = vp[lane + 32 * k];
    }

    // scores[l] = selu( sum_h selu(WE[b,l,h] + WD[bt,h]) * V[h] ), l in [X,512)
    for (int i = warp; X + i < Ll; i += 8) {
        const int l = X + i;
        const float4* wep = (const float4*)(g_WE + ((size_t)(b * Ll + l)) * Hdim);
        float s = 0.f;
#pragma unroll
        for (int k = 0; k < 6; k++) {
            float4 w = wep[lane + 32 * k];
            s = fmaf(selu1(w.x + wdf[k].x), vf[k].x, s);
            s = fmaf(selu1(w.y + wdf[k].y), vf[k].y, s);
            s = fmaf(selu1(w.z + wdf[k].z), vf[k].z, s);
            s = fmaf(selu1(w.w + wdf[k].w), vf[k].w, s);
        }
#pragma unroll
        for (int o = 16; o > 0; o >>= 1)
            s += __shfl_xor_sync(0xffffffffu, s, o);
        if (lane == 0) scores[l] = selu1(s);
    }
    __syncthreads();

    // masked max over [X, 512): per-thread strided, warp shuffle, cross-warp
    float m = -3.4e38f;
    for (int l = X + tid; l < Ll; l += 256) m = fmaxf(m, scores[l]);
#pragma unroll
    for (int o = 16; o > 0; o >>= 1)
        m = fmaxf(m, __shfl_xor_sync(0xffffffffu, m, o));
    if (lane == 0) redm[warp] = m;
    __syncthreads();
    float mx = fmaxf(fmaxf(fmaxf(redm[0], redm[1]), fmaxf(redm[2], redm[3])),
                     fmaxf(fmaxf(redm[4], redm[5]), fmaxf(redm[6], redm[7])));

    // sum of exp
    float sm = 0.f;
    for (int l = X + tid; l < Ll; l += 256) sm += __expf(scores[l] - mx);
#pragma unroll
    for (int o = 16; o > 0; o >>= 1)
        sm += __shfl_xor_sync(0xffffffffu, sm, o);
    if (lane == 0) reds[warp] = sm;
    __syncthreads();

    if (tid == 0) {
        float tot = reds[0] + reds[1] + reds[2] + reds[3]
                  + reds[4] + reds[5] + reds[6] + reds[7];
        float lse  = mx + __logf(tot);
        float gold = scores[Y];
        atomicAdd(out, (lse - gold) * (1.0f / (Bb * Tt)));
    }
}

__global__ void init_out_kernel(float* out) { out[0] = 0.f; }

// ---------------------------------------------------------------------------
extern "C" void kernel_launch(void* const* d_in, const int* in_sizes, int n_in,
                              void* d_out, int out_size) {
    const float* hn  = (const float*)d_in[0];
    const float* dec = (const float*)d_in[1];
    const float* W1  = (const float*)d_in[2];
    const float* W2  = (const float*)d_in[3];
    const float* V   = (const float*)d_in[4];
    const int*   Xi  = (const int*)d_in[5];
    const int*   Yi  = (const int*)d_in[6];
    // d_in[7] = lens (always L=512; unused)
    float* out = (float*)d_out;

    init_out_kernel<<<1, 1>>>(out);
    we_gemm_kernel<<<dim3(Hdim / 128, (Bb * Ll) / 128), 256>>>(hn, W1);
    wd_gemm_kernel<<<dim3(Hdim / 64, (Bb * Tt) / 64), 256>>>(dec, W2, Xi, Yi);
    pointer_kernel<<<Bb * Tt, 256>>>(V, Xi, Yi, out);
}

// round 3
// speedup vs baseline: 1.8888x; 1.8888x over previous
#include <cuda_runtime.h>
#include <math.h>

// Problem constants
#define Bb   16
#define Tt   16
#define Ll   512
#define Hdim 768

// SELU constants (jax.nn.selu)
#define SELU_SCALE 1.0507009873554805f
#define SELU_SA    1.7580993408473766f   // scale * alpha

// Scratch (device globals; no runtime allocation)
__device__ float g_WE[(size_t)Bb * Ll * Hdim];   // [B*L, H] = hn @ W1^T
__device__ float g_WD[(size_t)Bb * Tt * Hdim];   // [B*T, H] = dj @ W2^T
__device__ float g_S [(size_t)Bb * Tt * Ll];     // [B*T, L] pointer scores

// Detect index dtype: int32 -> word[1] = Xindex[0,1] = 32 (nonzero);
// int64 little-endian -> word[1] is the high word of Xindex[0,0] = 0.
__device__ __forceinline__ int idx_stride(const int* __restrict__ xp) {
    return (xp[1] == 0) ? 2 : 1;
}

// ---- packed f32x2 helpers (FFMA2: only reachable via PTX fma.rn.f32x2) ----
__device__ __forceinline__ unsigned long long pack_dup(float a) {
    unsigned long long r;
    asm("mov.b64 %0, {%1, %1};" : "=l"(r) : "f"(a));
    return r;
}
__device__ __forceinline__ void ffma2(unsigned long long& acc,
                                      unsigned long long a,
                                      unsigned long long b) {
    asm("fma.rn.f32x2 %0, %1, %2, %0;" : "+l"(acc) : "l"(a), "l"(b));
}
__device__ __forceinline__ float2 unpack2(unsigned long long v) {
    float lo, hi;
    asm("mov.b64 {%0, %1}, %2;" : "=f"(lo), "=f"(hi) : "l"(v));
    return make_float2(lo, hi);
}

// ---------------------------------------------------------------------------
// Kernel A: WE = hn @ W1^T   (M=8192, N=768, K=768)
// 128x128 tile, BK=16, 256 threads, 8x8 microtile via FFMA2 (8x4 packed).
// Global->reg prefetch overlaps next tile's LDGs with current compute.
// ---------------------------------------------------------------------------
__global__ __launch_bounds__(256) void we_gemm_kernel(
    const float* __restrict__ A,   // hn [8192, 768]
    const float* __restrict__ W)   // W1 [768, 768]
{
    __shared__ float As[16][132];
    __shared__ float Bs[16][132];

    const int tid = threadIdx.x;
    const int m0 = blockIdx.y * 128;
    const int n0 = blockIdx.x * 128;
    const int tm = (tid >> 4) * 8;
    const int tn = (tid & 15) * 8;

    // Per-thread load slots (2 A rows + 2 B rows per tile)
    const int row0 = tid >> 2;                 // 0..63
    const int row1 = (tid + 256) >> 2;         // 64..127
    const int kg0  = (tid & 3) * 4;
    const int kg1  = kg0;                      // (tid+256)&3 == tid&3
    const float* a0p = A + (size_t)(m0 + row0) * Hdim + kg0;
    const float* a1p = A + (size_t)(m0 + row1) * Hdim + kg1;
    const float* b0p = W + (size_t)(n0 + row0) * Hdim + kg0;
    const float* b1p = W + (size_t)(n0 + row1) * Hdim + kg1;

    unsigned long long acc[8][4];
#pragma unroll
    for (int i = 0; i < 8; i++)
#pragma unroll
        for (int j = 0; j < 4; j++) acc[i][j] = 0ull;

    // prefetch tile 0
    float4 pa0 = *(const float4*)(a0p);
    float4 pa1 = *(const float4*)(a1p);
    float4 pb0 = *(const float4*)(b0p);
    float4 pb1 = *(const float4*)(b1p);

    for (int k0 = 0; k0 < Hdim; k0 += 16) {
        // stage prefetched regs into smem
        As[kg0 + 0][row0] = pa0.x; As[kg0 + 1][row0] = pa0.y;
        As[kg0 + 2][row0] = pa0.z; As[kg0 + 3][row0] = pa0.w;
        As[kg1 + 0][row1] = pa1.x; As[kg1 + 1][row1] = pa1.y;
        As[kg1 + 2][row1] = pa1.z; As[kg1 + 3][row1] = pa1.w;
        Bs[kg0 + 0][row0] = pb0.x; Bs[kg0 + 1][row0] = pb0.y;
        Bs[kg0 + 2][row0] = pb0.z; Bs[kg0 + 3][row0] = pb0.w;
        Bs[kg1 + 0][row1] = pb1.x; Bs[kg1 + 1][row1] = pb1.y;
        Bs[kg1 + 2][row1] = pb1.z; Bs[kg1 + 3][row1] = pb1.w;
        __syncthreads();

        // launch next tile's loads (in flight during compute)
        if (k0 + 16 < Hdim) {
            pa0 = *(const float4*)(a0p + k0 + 16);
            pa1 = *(const float4*)(a1p + k0 + 16);
            pb0 = *(const float4*)(b0p + k0 + 16);
            pb1 = *(const float4*)(b1p + k0 + 16);
        }

#pragma unroll
        for (int kk = 0; kk < 16; kk++) {
            float a_[8];
            *(float4*)&a_[0] = *(const float4*)&As[kk][tm];
            *(float4*)&a_[4] = *(const float4*)&As[kk][tm + 4];
            // b column-pairs read directly as 64-bit lanes (32B-aligned)
            ulonglong2 bq0 = *(const ulonglong2*)&Bs[kk][tn];
            ulonglong2 bq1 = *(const ulonglong2*)&Bs[kk][tn + 4];
            unsigned long long b2[4] = {bq0.x, bq0.y, bq1.x, bq1.y};
#pragma unroll
            for (int i = 0; i < 8; i++) {
                unsigned long long ad = pack_dup(a_[i]);
#pragma unroll
                for (int j = 0; j < 4; j++) ffma2(acc[i][j], ad, b2[j]);
            }
        }
        __syncthreads();
    }

#pragma unroll
    for (int i = 0; i < 8; i++) {
        float2 c0 = unpack2(acc[i][0]);
        float2 c1 = unpack2(acc[i][1]);
        float2 c2 = unpack2(acc[i][2]);
        float2 c3 = unpack2(acc[i][3]);
        float4 o0 = make_float4(c0.x, c0.y, c1.x, c1.y);
        float4 o1 = make_float4(c2.x, c2.y, c3.x, c3.y);
        float* cp = g_WE + (size_t)(m0 + tm + i) * Hdim + n0 + tn;
        *(float4*)(cp)     = o0;
        *(float4*)(cp + 4) = o1;
    }
}

// ---------------------------------------------------------------------------
// Kernel B: WD[r,:] = decoder_out[b, Yindex[b,t], :] @ W2^T
// M=256 (gathered rows), N=768, K=768. 64x64 tile, BK=16, 4x4 microtile.
// ---------------------------------------------------------------------------
__global__ __launch_bounds__(256) void wd_gemm_kernel(
    const float* __restrict__ D,    // decoder_out [16, 512, 768]
    const float* __restrict__ W2,   // [768, 768]
    const int*   __restrict__ xp,
    const int*   __restrict__ yp)
{
    __shared__ float As[16][68];
    __shared__ float Bs[16][68];

    const int st  = idx_stride(xp);
    const int tid = threadIdx.x;
    const int m0  = blockIdx.y * 64;
    const int n0  = blockIdx.x * 64;
    const int tm  = (tid >> 4) * 4;
    const int tn  = (tid & 15) * 4;

    const int row = tid >> 2;
    const int kg  = (tid & 3) * 4;
    const int r   = m0 + row;                 // global (b*T+t) row 0..255
    const int bi  = r >> 4;
    const int Yv  = yp[r * st];
    const float* arow = D + ((size_t)bi * Ll + (size_t)Yv) * Hdim;
    const float* brow = W2 + (size_t)(n0 + row) * Hdim;

    float acc[4][4];
#pragma unroll
    for (int i = 0; i < 4; i++)
#pragma unroll
        for (int j = 0; j < 4; j++) acc[i][j] = 0.f;

    for (int k0 = 0; k0 < Hdim; k0 += 16) {
        float4 va = *(const float4*)(arow + k0 + kg);
        As[kg + 0][row] = va.x; As[kg + 1][row] = va.y;
        As[kg + 2][row] = va.z; As[kg + 3][row] = va.w;
        float4 vb = *(const float4*)(brow + k0 + kg);
        Bs[kg + 0][row] = vb.x; Bs[kg + 1][row] = vb.y;
        Bs[kg + 2][row] = vb.z; Bs[kg + 3][row] = vb.w;
        __syncthreads();

#pragma unroll
        for (int kk = 0; kk < 16; kk++) {
            float a[4], b[4];
            *(float4*)&a[0] = *(const float4*)&As[kk][tm];
            *(float4*)&b[0] = *(const float4*)&Bs[kk][tn];
#pragma unroll
            for (int i = 0; i < 4; i++)
#pragma unroll
                for (int j = 0; j < 4; j++)
                    acc[i][j] = fmaf(a[i], b[j], acc[i][j]);
        }
        __syncthreads();
    }

#pragma unroll
    for (int i = 0; i < 4; i++) {
        float4 o;
        o.x = acc[i][0]; o.y = acc[i][1]; o.z = acc[i][2]; o.w = acc[i][3];
        *(float4*)(g_WD + (size_t)(m0 + tm + i) * Hdim + n0 + tn) = o;
    }
}

// ---------------------------------------------------------------------------
// Kernel C1: pointer scores into g_S. grid (256, 2): block y takes l-parity.
// 4 independent accumulators break the serial FMA chain.
// ---------------------------------------------------------------------------
__device__ __forceinline__ float selu1(float x) {
    float e = __expf(x);
    return (x > 0.f) ? SELU_SCALE * x : fmaf(SELU_SA, e, -SELU_SA);
}

__global__ __launch_bounds__(256) void score_kernel(
    const float* __restrict__ V,
    const int*   __restrict__ xp)
{
    const int bt   = blockIdx.x;          // b*T + t
    const int half = blockIdx.y;          // l parity
    const int b    = bt >> 4;
    const int tid  = threadIdx.x;
    const int lane = tid & 31;
    const int warp = tid >> 5;

    const int st = idx_stride(xp);
    const int X  = xp[bt * st];

    // Per-lane fragments of WD[bt,:] and V: h = 4*(lane + 32*k)
    float4 wdf[6], vf[6];
    const float4* wdp = (const float4*)(g_WD + (size_t)bt * Hdim);
    const float4* vp  = (const float4*)V;
#pragma unroll
    for (int k = 0; k < 6; k++) {
        wdf[k] = wdp[lane + 32 * k];
        vf[k]  = vp[lane + 32 * k];
    }

    float* srow = g_S + (size_t)bt * Ll;

    for (int j = half + 2 * warp; X + j < Ll; j += 16) {
        const int l = X + j;
        const float4* wep = (const float4*)(g_WE + ((size_t)(b * Ll + l)) * Hdim);
        float s0 = 0.f, s1 = 0.f, s2 = 0.f, s3 = 0.f;
#pragma unroll
        for (int k = 0; k < 6; k++) {
            float4 w = wep[lane + 32 * k];
            s0 = fmaf(selu1(w.x + wdf[k].x), vf[k].x, s0);
            s1 = fmaf(selu1(w.y + wdf[k].y), vf[k].y, s1);
            s2 = fmaf(selu1(w.z + wdf[k].z), vf[k].z, s2);
            s3 = fmaf(selu1(w.w + wdf[k].w), vf[k].w, s3);
        }
        float s = (s0 + s1) + (s2 + s3);
#pragma unroll
        for (int o = 16; o > 0; o >>= 1)
            s += __shfl_xor_sync(0xffffffffu, s, o);
        if (lane == 0) srow[l] = selu1(s);
    }
}

// ---------------------------------------------------------------------------
// Kernel C2: masked log-softmax + NLL from g_S. One block per (b,t).
// ---------------------------------------------------------------------------
__global__ __launch_bounds__(256) void loss_kernel(
    const int* __restrict__ xp,
    const int* __restrict__ yp,
    float*     __restrict__ out)
{
    __shared__ float redm[8];
    __shared__ float reds[8];

    const int bt   = blockIdx.x;
    const int tid  = threadIdx.x;
    const int lane = tid & 31;
    const int warp = tid >> 5;

    const int st = idx_stride(xp);
    const int X  = xp[bt * st];
    const int Y  = yp[bt * st];
    const float* srow = g_S + (size_t)bt * Ll;

    float m = -3.4e38f;
    for (int l = X + tid; l < Ll; l += 256) m = fmaxf(m, srow[l]);
#pragma unroll
    for (int o = 16; o > 0; o >>= 1)
        m = fmaxf(m, __shfl_xor_sync(0xffffffffu, m, o));
    if (lane == 0) redm[warp] = m;
    __syncthreads();
    float mx = fmaxf(fmaxf(fmaxf(redm[0], redm[1]), fmaxf(redm[2], redm[3])),
                     fmaxf(fmaxf(redm[4], redm[5]), fmaxf(redm[6], redm[7])));

    float sm = 0.f;
    for (int l = X + tid; l < Ll; l += 256) sm += __expf(srow[l] - mx);
#pragma unroll
    for (int o = 16; o > 0; o >>= 1)
        sm += __shfl_xor_sync(0xffffffffu, sm, o);
    if (lane == 0) reds[warp] = sm;
    __syncthreads();

    if (tid == 0) {
        float tot = reds[0] + reds[1] + reds[2] + reds[3]
                  + reds[4] + reds[5] + reds[6] + reds[7];
        float lse  = mx + __logf(tot);
        float gold = srow[Y];
        atomicAdd(out, (lse - gold) * (1.0f / (Bb * Tt)));
    }
}

__global__ void init_out_kernel(float* out) { out[0] = 0.f; }

// ---------------------------------------------------------------------------
extern "C" void kernel_launch(void* const* d_in, const int* in_sizes, int n_in,
                              void* d_out, int out_size) {
    const float* hn  = (const float*)d_in[0];
    const float* dec = (const float*)d_in[1];
    const float* W1  = (const float*)d_in[2];
    const float* W2  = (const float*)d_in[3];
    const float* V   = (const float*)d_in[4];
    const int*   Xi  = (const int*)d_in[5];
    const int*   Yi  = (const int*)d_in[6];
    // d_in[7] = lens (always L=512; unused)
    float* out = (float*)d_out;

    init_out_kernel<<<1, 1>>>(out);
    we_gemm_kernel<<<dim3(Hdim / 128, (Bb * Ll) / 128), 256>>>(hn, W1);
    wd_gemm_kernel<<<dim3(Hdim / 64, (Bb * Tt) / 64), 256>>>(dec, W2, Xi, Yi);
    score_kernel<<<dim3(Bb * Tt, 2), 256>>>(V, Xi);
    loss_kernel<<<Bb * Tt, 256>>>(Xi, Yi, out);
}

// round 7
// speedup vs baseline: 2.7599x; 1.4612x over previous
#include <cuda_runtime.h>
#include <cuda_bf16.h>
#include <cstdint>
#include <math.h>

// Problem constants
#define Bb   16
#define Tt   16
#define Ll   512
#define Hdim 768
#define ML   (Bb * Ll)            // 8192 rows of hn

#define SELU_SCALE 1.0507009873554805f
#define SELU_SA    1.7580993408473766f   // scale * alpha

// Scratch (device globals; no runtime allocation)
__device__ float g_WET[(size_t)Hdim * ML];              // WE^T: [H, B*L]
__device__ float g_WD [(size_t)Bb * Tt * Hdim];         // [B*T, H]
__device__ __nv_bfloat16 g_Ah[(size_t)ML * Hdim];       // hn hi
__device__ __nv_bfloat16 g_Al[(size_t)ML * Hdim];       // hn lo
__device__ __nv_bfloat16 g_Bh[(size_t)Hdim * Hdim];     // W1 hi
__device__ __nv_bfloat16 g_Bl[(size_t)Hdim * Hdim];     // W1 lo

__device__ __forceinline__ int idx_stride(const int* __restrict__ xp) {
    return (xp[1] == 0) ? 2 : 1;   // int64 vs int32 index dtype
}

__device__ __forceinline__ uint32_t smem_u32(const void* p) {
    uint32_t a;
    asm("{ .reg .u64 t; cvta.to.shared.u64 t, %1; cvt.u32.u64 %0, t; }"
        : "=r"(a) : "l"(p));
    return a;
}
__device__ __forceinline__ void cp_async16(uint32_t sa, const void* ga) {
    asm volatile("cp.async.cg.shared.global [%0], [%1], 16;"
                 :: "r"(sa), "l"(ga) : "memory");
}
__device__ __forceinline__ void cp_commit() {
    asm volatile("cp.async.commit_group;" ::: "memory");
}
__device__ __forceinline__ void cp_wait0() {
    asm volatile("cp.async.wait_group 0;" ::: "memory");
}
__device__ __forceinline__ void ldsm_x4(uint32_t* r, uint32_t addr) {
    asm volatile("ldmatrix.sync.aligned.m8n8.x4.shared.b16 {%0,%1,%2,%3}, [%4];"
                 : "=r"(r[0]), "=r"(r[1]), "=r"(r[2]), "=r"(r[3]) : "r"(addr));
}
__device__ __forceinline__ void mma_bf16(float* c, const uint32_t* a, const uint32_t* b) {
    asm volatile(
        "mma.sync.aligned.m16n8k16.row.col.f32.bf16.bf16.f32 "
        "{%0,%1,%2,%3}, {%4,%5,%6,%7}, {%8,%9}, {%0,%1,%2,%3};"
        : "+f"(c[0]), "+f"(c[1]), "+f"(c[2]), "+f"(c[3])
        : "r"(a[0]), "r"(a[1]), "r"(a[2]), "r"(a[3]), "r"(b[0]), "r"(b[1]));
}

// ---------------------------------------------------------------------------
// fp32 -> (bf16 hi, bf16 lo) split, vectorized by float4
// ---------------------------------------------------------------------------
__global__ __launch_bounds__(256) void split_kernel(
    const float* __restrict__ src, __nv_bfloat16* __restrict__ hi,
    __nv_bfloat16* __restrict__ lo, int n4)
{
    int i = blockIdx.x * 256 + threadIdx.x;
    if (i >= n4) return;
    float4 v = ((const float4*)src)[i];
    float f[4] = {v.x, v.y, v.z, v.w};
    __nv_bfloat16 h[4], l[4];
#pragma unroll
    for (int j = 0; j < 4; j++) {
        h[j] = __float2bfloat16(f[j]);
        l[j] = __float2bfloat16(f[j] - __bfloat162float(h[j]));
    }
    __nv_bfloat162 h0; h0.x = h[0]; h0.y = h[1];
    __nv_bfloat162 h1; h1.x = h[2]; h1.y = h[3];
    __nv_bfloat162 l0; l0.x = l[0]; l0.y = l[1];
    __nv_bfloat162 l1; l1.x = l[2]; l1.y = l[3];
    ((__nv_bfloat162*)hi)[2 * i]     = h0;
    ((__nv_bfloat162*)hi)[2 * i + 1] = h1;
    ((__nv_bfloat162*)lo)[2 * i]     = l0;
    ((__nv_bfloat162*)lo)[2 * i + 1] = l1;
}

// ---------------------------------------------------------------------------
// Kernel A: WE^T = (hn @ W1^T)^T via mma.sync bf16 split (AhBh + AhBl + AlBh).
// CTA tile 128(m) x 128(n), BK=32, 8 warps each 64x32, cp.async 2-stage.
// smem stage layout (row stride 80B = 40 bf16, conflict-free for ldmatrix):
//   Ah @ 0, Al @ 10240, Bh @ 20480, Bl @ 30720 ; stage size 40960, 2 stages.
// Epilogue: stage D (128x128 f32) in smem, write transposed coalesced.
// ---------------------------------------------------------------------------
#define ROWB      80
#define TILEB     (128 * ROWB)       // 10240
#define STAGEB    (4 * TILEB)        // 40960
#define WE_SMEM   (2 * STAGEB)       // 81920 >= 128*132*4 epilogue

__global__ __launch_bounds__(256) void we_mma_kernel()
{
    extern __shared__ char smem[];
    const uint32_t sb = smem_u32(smem);

    const int tid    = threadIdx.x;
    const int lane   = tid & 31;
    const int wid    = tid >> 5;
    const int m0     = blockIdx.y * 128;
    const int n0     = blockIdx.x * 128;
    const int warp_m = (wid & 1) * 64;
    const int warp_n = (wid >> 1) * 32;

    // ldmatrix per-lane row/seg constants
    const int a_row = lane & 15;            // row within 16
    const int a_ks  = lane >> 4;            // 16B seg within k16
    const int b_row = lane & 7;
    const int b_nt  = (lane >> 4);          // 0..1 (n-subtile within pair)
    const int b_ks  = (lane >> 3) & 1;      // 16B seg

    float acc[4][4][4];
#pragma unroll
    for (int i = 0; i < 4; i++)
#pragma unroll
        for (int j = 0; j < 4; j++)
#pragma unroll
            for (int q = 0; q < 4; q++) acc[i][j][q] = 0.f;

    // cp.async per-thread segments: per tile 512 segs (128 rows x 4 x 16B)
    const int r0 = tid >> 2, r1 = (tid + 256) >> 2;
    const int g0 = (tid & 3), g1 = (tid & 3);

    const __nv_bfloat16* srcs[4] = {
        g_Ah + (size_t)m0 * Hdim, g_Al + (size_t)m0 * Hdim,
        g_Bh + (size_t)n0 * Hdim, g_Bl + (size_t)n0 * Hdim };

    auto issue_stage = [&](int s, int c) {
        const uint32_t stb = sb + s * STAGEB;
#pragma unroll
        for (int t = 0; t < 4; t++) {
            const __nv_bfloat16* g = srcs[t] + c * 32;
            cp_async16(stb + t * TILEB + r0 * ROWB + g0 * 16,
                       g + (size_t)r0 * Hdim + g0 * 8);
            cp_async16(stb + t * TILEB + r1 * ROWB + g1 * 16,
                       g + (size_t)r1 * Hdim + g1 * 8);
        }
        cp_commit();
    };

    issue_stage(0, 0);

    for (int c = 0; c < 24; c++) {
        const int s = c & 1;
        cp_wait0();
        __syncthreads();
        if (c + 1 < 24) issue_stage(s ^ 1, c + 1);

        const uint32_t stb = sb + s * STAGEB;
#pragma unroll
        for (int ks = 0; ks < 2; ks++) {
            uint32_t af[4][4], bh[4][2], bl[4][2];
            // A-hi fragments (4 m-tiles)
#pragma unroll
            for (int mt = 0; mt < 4; mt++)
                ldsm_x4(af[mt], stb + 0 * TILEB +
                        (warp_m + mt * 16 + a_row) * ROWB + ks * 32 + a_ks * 16);
            // B fragments: 2 x4 per matrix, each covers 2 n-subtiles
#pragma unroll
            for (int q = 0; q < 2; q++) {
                uint32_t t4[4];
                ldsm_x4(t4, stb + 2 * TILEB +
                        (warp_n + q * 16 + b_nt * 8 + b_row) * ROWB + ks * 32 + b_ks * 16);
                bh[2 * q][0] = t4[0]; bh[2 * q][1] = t4[1];
                bh[2 * q + 1][0] = t4[2]; bh[2 * q + 1][1] = t4[3];
                ldsm_x4(t4, stb + 3 * TILEB +
                        (warp_n + q * 16 + b_nt * 8 + b_row) * ROWB + ks * 32 + b_ks * 16);
                bl[2 * q][0] = t4[0]; bl[2 * q][1] = t4[1];
                bl[2 * q + 1][0] = t4[2]; bl[2 * q + 1][1] = t4[3];
            }
            // Ah*Bh + Ah*Bl
#pragma unroll
            for (int mt = 0; mt < 4; mt++)
#pragma unroll
                for (int nt = 0; nt < 4; nt++) {
                    mma_bf16(acc[mt][nt], af[mt], bh[nt]);
                    mma_bf16(acc[mt][nt], af[mt], bl[nt]);
                }
            // Al*Bh (reuse af regs)
#pragma unroll
            for (int mt = 0; mt < 4; mt++)
                ldsm_x4(af[mt], stb + 1 * TILEB +
                        (warp_m + mt * 16 + a_row) * ROWB + ks * 32 + a_ks * 16);
#pragma unroll
            for (int mt = 0; mt < 4; mt++)
#pragma unroll
                for (int nt = 0; nt < 4; nt++)
                    mma_bf16(acc[mt][nt], af[mt], bh[nt]);
        }
    }
    __syncthreads();

    // Epilogue: D -> smem [m][n] (stride 132), then transposed coalesced store
    float (*smT)[132] = (float (*)[132])smem;
    {
        const int rq = lane >> 2;          // row within 8
        const int cq = 2 * (lane & 3);     // col pair
#pragma unroll
        for (int mt = 0; mt < 4; mt++)
#pragma unroll
            for (int nt = 0; nt < 4; nt++) {
                const int mm = warp_m + mt * 16 + rq;
                const int nn = warp_n + nt * 8 + cq;
                smT[mm][nn]         = acc[mt][nt][0];
                smT[mm][nn + 1]     = acc[mt][nt][1];
                smT[mm + 8][nn]     = acc[mt][nt][2];
                smT[mm + 8][nn + 1] = acc[mt][nt][3];
            }
    }
    __syncthreads();

    // WE^T[h = n0+hh][m0 + mm]: warp handles 16 h-rows, lane writes float4 of m
#pragma unroll
    for (int rr = 0; rr < 16; rr++) {
        const int hh = wid * 16 + rr;
        float4 v;
        v.x = smT[lane * 4 + 0][hh];
        v.y = smT[lane * 4 + 1][hh];
        v.z = smT[lane * 4 + 2][hh];
        v.w = smT[lane * 4 + 3][hh];
        *(float4*)(g_WET + (size_t)(n0 + hh) * ML + m0 + lane * 4) = v;
    }
}

// ---------------------------------------------------------------------------
// Kernel B: WD[r,:] = decoder_out[b, Yindex[b,t], :] @ W2^T (fp32 scalar)
// ---------------------------------------------------------------------------
__global__ __launch_bounds__(256) void wd_gemm_kernel(
    const float* __restrict__ D, const float* __restrict__ W2,
    const int* __restrict__ xp, const int* __restrict__ yp)
{
    __shared__ float As[16][68];
    __shared__ float Bs[16][68];

    const int st  = idx_stride(xp);
    const int tid = threadIdx.x;
    const int m0  = blockIdx.y * 64;
    const int n0  = blockIdx.x * 64;
    const int tm  = (tid >> 4) * 4;
    const int tn  = (tid & 15) * 4;

    const int row = tid >> 2;
    const int kg  = (tid & 3) * 4;
    const int r   = m0 + row;
    const int bi  = r >> 4;
    const int Yv  = yp[r * st];
    const float* arow = D + ((size_t)bi * Ll + (size_t)Yv) * Hdim;
    const float* brow = W2 + (size_t)(n0 + row) * Hdim;

    float acc[4][4];
#pragma unroll
    for (int i = 0; i < 4; i++)
#pragma unroll
        for (int j = 0; j < 4; j++) acc[i][j] = 0.f;

    for (int k0 = 0; k0 < Hdim; k0 += 16) {
        float4 va = *(const float4*)(arow + k0 + kg);
        As[kg + 0][row] = va.x; As[kg + 1][row] = va.y;
        As[kg + 2][row] = va.z; As[kg + 3][row] = va.w;
        float4 vb = *(const float4*)(brow + k0 + kg);
        Bs[kg + 0][row] = vb.x; Bs[kg + 1][row] = vb.y;
        Bs[kg + 2][row] = vb.z; Bs[kg + 3][row] = vb.w;
        __syncthreads();

#pragma unroll
        for (int kk = 0; kk < 16; kk++) {
            float a[4], b[4];
            *(float4*)&a[0] = *(const float4*)&As[kk][tm];
            *(float4*)&b[0] = *(const float4*)&Bs[kk][tn];
#pragma unroll
            for (int i = 0; i < 4; i++)
#pragma unroll
                for (int j = 0; j < 4; j++)
                    acc[i][j] = fmaf(a[i], b[j], acc[i][j]);
        }
        __syncthreads();
    }

#pragma unroll
    for (int i = 0; i < 4; i++) {
        float4 o;
        o.x = acc[i][0]; o.y = acc[i][1]; o.z = acc[i][2]; o.w = acc[i][3];
        *(float4*)(g_WD + (size_t)(m0 + tm + i) * Hdim + n0 + tn) = o;
    }
}

// ---------------------------------------------------------------------------
// Kernel C: fused scores + masked log-softmax + NLL. One block per (b,t),
// 512 threads, thread per l reading WE^T columns (coalesced).
// ---------------------------------------------------------------------------
__device__ __forceinline__ float selu1(float x) {
    float e = __expf(x);
    return (x > 0.f) ? SELU_SCALE * x : fmaf(SELU_SA, e, -SELU_SA);
}

__global__ __launch_bounds__(512) void score_loss_kernel(
    const float* __restrict__ V,
    const int* __restrict__ xp, const int* __restrict__ yp,
    float* __restrict__ out)
{
    __shared__ float wd_s[Hdim];
    __shared__ float v_s[Hdim];
    __shared__ float red[16];
    __shared__ float bcast;
    __shared__ float gold_s;

    const int bt   = blockIdx.x;
    const int b    = bt >> 4;
    const int tid  = threadIdx.x;
    const int lane = tid & 31;
    const int warp = tid >> 5;

    const int st = idx_stride(xp);
    const int X  = xp[bt * st];
    const int Y  = yp[bt * st];

    for (int i = tid; i < Hdim; i += 512) {
        wd_s[i] = g_WD[(size_t)bt * Hdim + i];
        v_s[i]  = V[i];
    }
    __syncthreads();

    const int  l      = X + tid;
    const bool active = (l < Ll);

    float sc = -3.4e38f;
    if (active) {
        const float* col = g_WET + (size_t)b * Ll + l;   // + h*ML per row
        float s0 = 0.f, s1 = 0.f, s2 = 0.f, s3 = 0.f;
#pragma unroll 4
        for (int h = 0; h < Hdim; h += 4) {
            float w0 = col[(size_t)(h + 0) * ML];
            float w1 = col[(size_t)(h + 1) * ML];
            float w2 = col[(size_t)(h + 2) * ML];
            float w3 = col[(size_t)(h + 3) * ML];
            s0 = fmaf(selu1(w0 + wd_s[h + 0]), v_s[h + 0], s0);
            s1 = fmaf(selu1(w1 + wd_s[h + 1]), v_s[h + 1], s1);
            s2 = fmaf(selu1(w2 + wd_s[h + 2]), v_s[h + 2], s2);
            s3 = fmaf(selu1(w3 + wd_s[h + 3]), v_s[h + 3], s3);
        }
        sc = selu1((s0 + s1) + (s2 + s3));
        if (l == Y) gold_s = sc;
    }

    // block max
    float m = sc;
#pragma unroll
    for (int o = 16; o > 0; o >>= 1)
        m = fmaxf(m, __shfl_xor_sync(0xffffffffu, m, o));
    if (lane == 0) red[warp] = m;
    __syncthreads();
    if (tid == 0) {
        float mm = red[0];
#pragma unroll
        for (int i = 1; i < 16; i++) mm = fmaxf(mm, red[i]);
        bcast = mm;
    }
    __syncthreads();
    const float mx = bcast;

    // block sum of exp
    float e = active ? __expf(sc - mx) : 0.f;
#pragma unroll
    for (int o = 16; o > 0; o >>= 1)
        e += __shfl_xor_sync(0xffffffffu, e, o);
    if (lane == 0) red[warp] = e;
    __syncthreads();

    if (tid == 0) {
        float tot = 0.f;
#pragma unroll
        for (int i = 0; i < 16; i++) tot += red[i];
        float lse = mx + __logf(tot);
        atomicAdd(out, (lse - gold_s) * (1.0f / (Bb * Tt)));
    }
}

__global__ void init_out_kernel(float* out) { out[0] = 0.f; }

// ---------------------------------------------------------------------------
extern "C" void kernel_launch(void* const* d_in, const int* in_sizes, int n_in,
                              void* d_out, int out_size) {
    const float* hn  = (const float*)d_in[0];
    const float* dec = (const float*)d_in[1];
    const float* W1  = (const float*)d_in[2];
    const float* W2  = (const float*)d_in[3];
    const float* V   = (const float*)d_in[4];
    const int*   Xi  = (const int*)d_in[5];
    const int*   Yi  = (const int*)d_in[6];
    float* out = (float*)d_out;

    cudaFuncSetAttribute(we_mma_kernel,
                         cudaFuncAttributeMaxDynamicSharedMemorySize, WE_SMEM);

    __nv_bfloat16 *ah, *al, *bh, *bl;
    cudaGetSymbolAddress((void**)&ah, g_Ah);
    cudaGetSymbolAddress((void**)&al, g_Al);
    cudaGetSymbolAddress((void**)&bh, g_Bh);
    cudaGetSymbolAddress((void**)&bl, g_Bl);

    init_out_kernel<<<1, 1>>>(out);

    const int nA4 = (ML * Hdim) / 4;
    const int nW4 = (Hdim * Hdim) / 4;
    split_kernel<<<(nA4 + 255) / 256, 256>>>(hn, ah, al, nA4);
    split_kernel<<<(nW4 + 255) / 256, 256>>>(W1, bh, bl, nW4);

    we_mma_kernel<<<dim3(Hdim / 128, ML / 128), 256, WE_SMEM>>>();
    wd_gemm_kernel<<<dim3(Hdim / 64, (Bb * Tt) / 64), 256>>>(dec, W2, Xi, Yi);
    score_loss_kernel<<<Bb * Tt, 512>>>(V, Xi, Yi, out);
}